// round 3
// baseline (speedup 1.0000x reference)
#include <cuda_runtime.h>
#include <math.h>

// Problem constants
#define HW     16384          // H*W
#define NB     256            // batch
#define NCH    3              // channels
#define NCLS   10             // classes
#define KS     4              // burnin * num_samples
#define NSTATE 5              // s0 + 4 candidates

// Tiling
#define PT     256            // pixels per tile (shared-W tile)
#define NTILES (HW / PT)      // 64
#define BPB    16             // batches per block
#define NGRP   (NB / BPB)     // 16
#define NVALS  (NSTATE * NB * NCLS)   // 12800

typedef unsigned long long u64;

// Deterministic scratch (no atomics): per-tile partial logits, then reduced.
__device__ float g_part[NTILES * NVALS];
__device__ float g_logits[NVALS];

// ---- packed f32x2 helpers (sm_103a) ----
__device__ __forceinline__ u64 pk2(float lo, float hi) {
    u64 r; asm("mov.b64 %0,{%1,%2};" : "=l"(r) : "f"(lo), "f"(hi)); return r;
}
__device__ __forceinline__ void up2(u64 v, float& lo, float& hi) {
    asm("mov.b64 {%0,%1},%2;" : "=f"(lo), "=f"(hi) : "l"(v));
}
__device__ __forceinline__ u64 fma2(u64 a, u64 b, u64 c) {
    u64 d; asm("fma.rn.f32x2 %0,%1,%2,%3;" : "=l"(d) : "l"(a), "l"(b), "l"(c)); return d;
}
__device__ __forceinline__ u64 mul2(u64 a, u64 b) {
    u64 d; asm("mul.rn.f32x2 %0,%1,%2;" : "=l"(d) : "l"(a), "l"(b)); return d;
}
__device__ __forceinline__ u64 add2(u64 a, u64 b) {
    u64 d; asm("add.rn.f32x2 %0,%1,%2;" : "=l"(d) : "l"(a), "l"(b)); return d;
}

// ============================================================================
// Kernel 1: fused masked-logits. One pass over x / zl / bern.
// grid = NTILES * NGRP blocks, 256 threads (8 warps).
// Block (tile, grp): caches W[tile] in SMEM, each warp handles 2 batches.
// Per pixel: q[nc] = sum_c x*W (shared), acc[state][nc] += mask_state * q[nc].
// Warp-reduces 25 f32x2 accumulators, writes per-tile partials (no atomics).
// ============================================================================
__global__ void __launch_bounds__(256) masked_logits_kernel(
    const float* __restrict__ zl, const float* __restrict__ x,
    const float* __restrict__ bern, const float* __restrict__ W)
{
    // W tile: [cj = c*5+j][i = p%4][ch = p/4], float2 of (nc=2j, 2j+1)
    // Lane-contiguous in ch -> conflict-free LDS.64.
    __shared__ float2 Wsh[15 * PT];

    int tile = blockIdx.x & (NTILES - 1);
    int grp  = blockIdx.x >> 6;            // / NTILES
    int p0   = tile * PT;
    int tid  = threadIdx.x;

    // Cooperative W load: 15*PT float2 = 3840 elems, 15 per thread.
    for (int e = tid; e < 15 * PT; e += 256) {
        int cj = e / PT;
        int p  = e - cj * PT;
        int c  = cj / 5, j = cj - c * 5;
        const float* wr = W + (size_t)(c * HW + p0 + p) * NCLS + 2 * j;
        Wsh[cj * PT + (p & 3) * (PT / 4) + (p >> 2)] = make_float2(wr[0], wr[1]);
    }
    __syncthreads();

    int warp = tid >> 5, lane = tid & 31;

    for (int bi = warp; bi < BPB; bi += 8) {
        int b = grp * BPB + bi;

        u64 acc[NSTATE][5];
        #pragma unroll
        for (int s = 0; s < NSTATE; s++)
            #pragma unroll
            for (int j = 0; j < 5; j++) acc[s][j] = 0ull;  // {+0.f,+0.f}

        const float* zb = zl   + (size_t)b * HW + p0;
        const float* xb = x    + (size_t)b * NCH * HW + p0;
        const float* eb = bern + (size_t)b * HW + p0;

        #pragma unroll
        for (int it = 0; it < PT / 128; ++it) {       // 2 chunks of 4 px per lane
            int ch = it * 32 + lane;
            int p  = ch * 4;
            float4 z4 = *(const float4*)(zb + p);
            float4 e0 = *(const float4*)(eb + (size_t)0 * NB * HW + p);
            float4 e1 = *(const float4*)(eb + (size_t)1 * NB * HW + p);
            float4 e2 = *(const float4*)(eb + (size_t)2 * NB * HW + p);
            float4 e3 = *(const float4*)(eb + (size_t)3 * NB * HW + p);
            float4 x0 = *(const float4*)(xb + 0 * HW + p);
            float4 x1 = *(const float4*)(xb + 1 * HW + p);
            float4 x2 = *(const float4*)(xb + 2 * HW + p);

            float zz[4]  = {z4.x, z4.y, z4.z, z4.w};
            float ee0[4] = {e0.x, e0.y, e0.z, e0.w};
            float ee1[4] = {e1.x, e1.y, e1.z, e1.w};
            float ee2[4] = {e2.x, e2.y, e2.z, e2.w};
            float ee3[4] = {e3.x, e3.y, e3.z, e3.w};
            float xx0[4] = {x0.x, x0.y, x0.z, x0.w};
            float xx1[4] = {x1.x, x1.y, x1.z, x1.w};
            float xx2[4] = {x2.x, x2.y, x2.z, x2.w};

            #pragma unroll
            for (int i = 0; i < 4; i++) {
                float zv = zz[i];
                float zp = 1.f / (1.f + expf(-zv));   // accurate sigmoid
                float m0 = (zv >= 0.f)  ? 1.f : 0.f;  // zp>=0.5  <=>  zl>=0
                float m1 = (ee0[i] < zp) ? 1.f : 0.f;
                float m2 = (ee1[i] < zp) ? 1.f : 0.f;
                float m3 = (ee2[i] < zp) ? 1.f : 0.f;
                float m4 = (ee3[i] < zp) ? 1.f : 0.f;
                u64 mm[NSTATE] = {pk2(m0, m0), pk2(m1, m1), pk2(m2, m2),
                                  pk2(m3, m3), pk2(m4, m4)};
                u64 xp0 = pk2(xx0[i], xx0[i]);
                u64 xp1 = pk2(xx1[i], xx1[i]);
                u64 xp2 = pk2(xx2[i], xx2[i]);

                const float2* wbase = Wsh + i * (PT / 4) + ch;
                #pragma unroll
                for (int j = 0; j < 5; j++) {
                    u64 w0 = *(const u64*)(wbase + (j)      * PT);
                    u64 w1 = *(const u64*)(wbase + (5 + j)  * PT);
                    u64 w2 = *(const u64*)(wbase + (10 + j) * PT);
                    u64 q = fma2(xp0, w0, fma2(xp1, w1, mul2(xp2, w2)));
                    #pragma unroll
                    for (int s = 0; s < NSTATE; s++)
                        acc[s][j] = fma2(mm[s], q, acc[s][j]);
                }
            }
        }

        // Warp butterfly reduce (deterministic pairwise tree)
        #pragma unroll
        for (int s = 0; s < NSTATE; s++)
            #pragma unroll
            for (int j = 0; j < 5; j++) {
                u64 v = acc[s][j];
                #pragma unroll
                for (int off = 16; off > 0; off >>= 1)
                    v = add2(v, __shfl_xor_sync(0xffffffffu, v, off));
                acc[s][j] = v;
            }

        if (lane < 25) {
            int s = lane / 5, j = lane - s * 5;
            float lo, hi;
            up2(acc[s][j], lo, hi);
            float* dst = g_part + (size_t)tile * NVALS + (s * NB + b) * NCLS + 2 * j;
            dst[0] = lo;
            dst[1] = hi;
        }
    }
}

// ============================================================================
// Kernel 2: reduce per-tile partials (fixed order -> deterministic).
// ============================================================================
__global__ void reduce_kernel() {
    int v = blockIdx.x * blockDim.x + threadIdx.x;   // 50*256 = 12800
    if (v < NVALS) {
        float s = 0.f;
        #pragma unroll 8
        for (int t = 0; t < NTILES; t++) s += g_part[(size_t)t * NVALS + v];
        g_logits[v] = s;
    }
}

// ============================================================================
// Kernel 3: log-softmax at label, 4-step MH chain, emit accepted state's
// raw logits (+bias). One thread per batch row.
// ============================================================================
__global__ void finalize_kernel(const int* __restrict__ y,
                                const float* __restrict__ u,
                                const float* __restrict__ bias,
                                float* __restrict__ out)
{
    int b = threadIdx.x;               // 256 threads, 1 block
    float lg[NSTATE][NCLS];
    #pragma unroll
    for (int s = 0; s < NSTATE; s++)
        #pragma unroll
        for (int j = 0; j < NCLS; j++)
            lg[s][j] = g_logits[(s * NB + b) * NCLS + j] + bias[j];

    int yb = y[b];
    float lp[NSTATE];
    #pragma unroll
    for (int s = 0; s < NSTATE; s++) {
        float mx = lg[s][0];
        #pragma unroll
        for (int j = 1; j < NCLS; j++) mx = fmaxf(mx, lg[s][j]);
        float sum = 0.f;
        #pragma unroll
        for (int j = 0; j < NCLS; j++) sum += expf(lg[s][j] - mx);
        lp[s] = lg[s][yb] - mx - logf(sum);
    }

    int sel = 0;
    float cur = lp[0];
    #pragma unroll
    for (int k = 1; k <= KS; k++) {
        float lu = logf(u[(k - 1) * NB + b]);
        if (lu <= lp[k] - cur) { sel = k; cur = lp[k]; }
    }

    #pragma unroll
    for (int j = 0; j < NCLS; j++)
        out[b * NCLS + j] = lg[sel][j];
}

// ============================================================================
// Launcher (graph-capturable: kernel launches only)
// ============================================================================
extern "C" void kernel_launch(void* const* d_in, const int* in_sizes, int n_in,
                              void* d_out, int out_size)
{
    const float *zl = nullptr, *x = nullptr, *bern = nullptr;
    const float *u = nullptr, *W = nullptr, *bias = nullptr;
    const int* y = nullptr;

    for (int i = 0; i < n_in; i++) {
        switch (in_sizes[i]) {
            case 4194304:  zl   = (const float*)d_in[i]; break;  // [256,1,128,128]
            case 12582912: x    = (const float*)d_in[i]; break;  // [256,3,128,128]
            case 256:      y    = (const int*)  d_in[i]; break;  // [256]
            case 16777216: bern = (const float*)d_in[i]; break;  // [4,256,1,128,128]
            case 1024:     u    = (const float*)d_in[i]; break;  // [4,256]
            case 491520:   W    = (const float*)d_in[i]; break;  // [49152,10]
            case 10:       bias = (const float*)d_in[i]; break;  // [10]
            default: break;
        }
    }

    masked_logits_kernel<<<NTILES * NGRP, 256>>>(zl, x, bern, W);
    reduce_kernel<<<(NVALS + 255) / 256, 256>>>();
    finalize_kernel<<<1, NB>>>(y, u, bias, (float*)d_out);
}

// round 6
// speedup vs baseline: 1.1984x; 1.1984x over previous
#include <cuda_runtime.h>
#include <math.h>

// Problem constants
#define HW     16384          // H*W
#define NB     256            // batch
#define NCH    3              // channels
#define NCLS   10             // classes
#define KS     4              // burnin * num_samples
#define NSTATE 5              // s0 + 4 candidates

// Tiling
#define PT     256            // pixels per tile (shared-W tile)
#define NTILES (HW / PT)      // 64
#define BPB    16             // batches per block
#define NGRP   (NB / BPB)     // 16
#define NVALS  (NSTATE * NB * NCLS)   // 12800

typedef unsigned long long u64;

// Deterministic scratch (no atomics): per-tile partial logits, then reduced.
__device__ float g_part[NTILES * NVALS];
__device__ float g_logits[NVALS];

// ---- packed f32x2 helpers (sm_103a) ----
__device__ __forceinline__ u64 pk2(float lo, float hi) {
    u64 r; asm("mov.b64 %0,{%1,%2};" : "=l"(r) : "f"(lo), "f"(hi)); return r;
}
__device__ __forceinline__ void up2(u64 v, float& lo, float& hi) {
    asm("mov.b64 {%0,%1},%2;" : "=f"(lo), "=f"(hi) : "l"(v));
}
__device__ __forceinline__ u64 fma2(u64 a, u64 b, u64 c) {
    u64 d; asm("fma.rn.f32x2 %0,%1,%2,%3;" : "=l"(d) : "l"(a), "l"(b), "l"(c)); return d;
}
__device__ __forceinline__ u64 mul2(u64 a, u64 b) {
    u64 d; asm("mul.rn.f32x2 %0,%1,%2;" : "=l"(d) : "l"(a), "l"(b)); return d;
}
__device__ __forceinline__ u64 add2(u64 a, u64 b) {
    u64 d; asm("add.rn.f32x2 %0,%1,%2;" : "=l"(d) : "l"(a), "l"(b)); return d;
}

// ============================================================================
// Kernel 1: fused masked-logits. One pass over x / zl / bern.
// grid = NTILES * NGRP blocks, 256 threads (8 warps), 2 CTAs/SM (forced).
// Block (tile, grp): caches W[tile] in SMEM, each warp handles 2 batches.
// Per pixel: q[nc] = sum_c x*W (shared), acc[state][nc] += mask_state * q[nc].
// Warp-reduces 25 f32x2 accumulators, writes per-tile partials (no atomics).
// ============================================================================
__global__ void __launch_bounds__(256, 2) masked_logits_kernel(
    const float* __restrict__ zl, const float* __restrict__ x,
    const float* __restrict__ bern, const float* __restrict__ W)
{
    // W tile: [cj = c*5+j][i = p%4][ch = p/4], float2 of (nc=2j, 2j+1)
    // Lane-contiguous in ch -> conflict-free LDS.64.
    __shared__ float2 Wsh[15 * PT];

    int tile = blockIdx.x & (NTILES - 1);
    int grp  = blockIdx.x >> 6;            // / NTILES
    int p0   = tile * PT;
    int tid  = threadIdx.x;

    // Cooperative W load: 15*PT float2 = 3840 elems, 15 per thread.
    for (int e = tid; e < 15 * PT; e += 256) {
        int cj = e / PT;
        int p  = e - cj * PT;
        int c  = cj / 5, j = cj - c * 5;
        const float* wr = W + (size_t)(c * HW + p0 + p) * NCLS + 2 * j;
        Wsh[cj * PT + (p & 3) * (PT / 4) + (p >> 2)] = make_float2(wr[0], wr[1]);
    }
    __syncthreads();

    int warp = tid >> 5, lane = tid & 31;

    for (int bi = warp; bi < BPB; bi += 8) {
        int b = grp * BPB + bi;

        u64 acc[NSTATE][5];
        #pragma unroll
        for (int s = 0; s < NSTATE; s++)
            #pragma unroll
            for (int j = 0; j < 5; j++) acc[s][j] = 0ull;  // {+0.f,+0.f}

        const float* zb = zl   + (size_t)b * HW + p0;
        const float* xb = x    + (size_t)b * NCH * HW + p0;
        const float* eb = bern + (size_t)b * HW + p0;

        #pragma unroll
        for (int it = 0; it < PT / 128; ++it) {       // 2 chunks of 4 px per lane
            int ch = it * 32 + lane;
            int p  = ch * 4;

            // Load mask inputs first and fold them into 20 mask floats so the
            // z/e float4s die before the x loads + FMA pipeline go live.
            float4 z4 = *(const float4*)(zb + p);
            float4 e0 = *(const float4*)(eb + (size_t)0 * NB * HW + p);
            float4 e1 = *(const float4*)(eb + (size_t)1 * NB * HW + p);
            float4 e2 = *(const float4*)(eb + (size_t)2 * NB * HW + p);
            float4 e3 = *(const float4*)(eb + (size_t)3 * NB * HW + p);

            float zz[4]  = {z4.x, z4.y, z4.z, z4.w};
            float ee0[4] = {e0.x, e0.y, e0.z, e0.w};
            float ee1[4] = {e1.x, e1.y, e1.z, e1.w};
            float ee2[4] = {e2.x, e2.y, e2.z, e2.w};
            float ee3[4] = {e3.x, e3.y, e3.z, e3.w};

            float mk[NSTATE][4];
            #pragma unroll
            for (int i = 0; i < 4; i++) {
                float zv = zz[i];
                float zp = 1.f / (1.f + expf(-zv));   // accurate sigmoid
                mk[0][i] = (zv >= 0.f)  ? 1.f : 0.f;  // zp>=0.5  <=>  zl>=0
                mk[1][i] = (ee0[i] < zp) ? 1.f : 0.f;
                mk[2][i] = (ee1[i] < zp) ? 1.f : 0.f;
                mk[3][i] = (ee2[i] < zp) ? 1.f : 0.f;
                mk[4][i] = (ee3[i] < zp) ? 1.f : 0.f;
            }

            float4 x0 = *(const float4*)(xb + 0 * HW + p);
            float4 x1 = *(const float4*)(xb + 1 * HW + p);
            float4 x2 = *(const float4*)(xb + 2 * HW + p);
            float xx0[4] = {x0.x, x0.y, x0.z, x0.w};
            float xx1[4] = {x1.x, x1.y, x1.z, x1.w};
            float xx2[4] = {x2.x, x2.y, x2.z, x2.w};

            #pragma unroll
            for (int i = 0; i < 4; i++) {
                u64 mm[NSTATE] = {pk2(mk[0][i], mk[0][i]), pk2(mk[1][i], mk[1][i]),
                                  pk2(mk[2][i], mk[2][i]), pk2(mk[3][i], mk[3][i]),
                                  pk2(mk[4][i], mk[4][i])};
                u64 xp0 = pk2(xx0[i], xx0[i]);
                u64 xp1 = pk2(xx1[i], xx1[i]);
                u64 xp2 = pk2(xx2[i], xx2[i]);

                const float2* wbase = Wsh + i * (PT / 4) + ch;
                #pragma unroll
                for (int j = 0; j < 5; j++) {
                    u64 w0 = *(const u64*)(wbase + (j)      * PT);
                    u64 w1 = *(const u64*)(wbase + (5 + j)  * PT);
                    u64 w2 = *(const u64*)(wbase + (10 + j) * PT);
                    u64 q = fma2(xp0, w0, fma2(xp1, w1, mul2(xp2, w2)));
                    #pragma unroll
                    for (int s = 0; s < NSTATE; s++)
                        acc[s][j] = fma2(mm[s], q, acc[s][j]);
                }
            }
        }

        // Warp butterfly reduce (deterministic pairwise tree)
        #pragma unroll
        for (int s = 0; s < NSTATE; s++)
            #pragma unroll
            for (int j = 0; j < 5; j++) {
                u64 v = acc[s][j];
                #pragma unroll
                for (int off = 16; off > 0; off >>= 1)
                    v = add2(v, __shfl_xor_sync(0xffffffffu, v, off));
                acc[s][j] = v;
            }

        if (lane < 25) {
            int s = lane / 5, j = lane - s * 5;
            float lo, hi;
            up2(acc[s][j], lo, hi);
            float* dst = g_part + (size_t)tile * NVALS + (s * NB + b) * NCLS + 2 * j;
            dst[0] = lo;
            dst[1] = hi;
        }
    }
}

// ============================================================================
// Kernel 2: reduce per-tile partials (fixed order -> deterministic).
// ============================================================================
__global__ void reduce_kernel() {
    int v = blockIdx.x * blockDim.x + threadIdx.x;   // 50*256 = 12800
    if (v < NVALS) {
        float s = 0.f;
        #pragma unroll 8
        for (int t = 0; t < NTILES; t++) s += g_part[(size_t)t * NVALS + v];
        g_logits[v] = s;
    }
}

// ============================================================================
// Kernel 3: log-softmax at label, 4-step MH chain, emit accepted state's
// raw logits (+bias). One thread per batch row.
// ============================================================================
__global__ void finalize_kernel(const int* __restrict__ y,
                                const float* __restrict__ u,
                                const float* __restrict__ bias,
                                float* __restrict__ out)
{
    int b = threadIdx.x;               // 256 threads, 1 block
    float lg[NSTATE][NCLS];
    #pragma unroll
    for (int s = 0; s < NSTATE; s++)
        #pragma unroll
        for (int j = 0; j < NCLS; j++)
            lg[s][j] = g_logits[(s * NB + b) * NCLS + j] + bias[j];

    int yb = y[b];
    float lp[NSTATE];
    #pragma unroll
    for (int s = 0; s < NSTATE; s++) {
        float mx = lg[s][0];
        #pragma unroll
        for (int j = 1; j < NCLS; j++) mx = fmaxf(mx, lg[s][j]);
        float sum = 0.f;
        #pragma unroll
        for (int j = 0; j < NCLS; j++) sum += expf(lg[s][j] - mx);
        lp[s] = lg[s][yb] - mx - logf(sum);
    }

    int sel = 0;
    float cur = lp[0];
    #pragma unroll
    for (int k = 1; k <= KS; k++) {
        float lu = logf(u[(k - 1) * NB + b]);
        if (lu <= lp[k] - cur) { sel = k; cur = lp[k]; }
    }

    #pragma unroll
    for (int j = 0; j < NCLS; j++)
        out[b * NCLS + j] = lg[sel][j];
}

// ============================================================================
// Launcher (graph-capturable: kernel launches only)
// ============================================================================
extern "C" void kernel_launch(void* const* d_in, const int* in_sizes, int n_in,
                              void* d_out, int out_size)
{
    const float *zl = nullptr, *x = nullptr, *bern = nullptr;
    const float *u = nullptr, *W = nullptr, *bias = nullptr;
    const int* y = nullptr;

    for (int i = 0; i < n_in; i++) {
        switch (in_sizes[i]) {
            case 4194304:  zl   = (const float*)d_in[i]; break;  // [256,1,128,128]
            case 12582912: x    = (const float*)d_in[i]; break;  // [256,3,128,128]
            case 256:      y    = (const int*)  d_in[i]; break;  // [256]
            case 16777216: bern = (const float*)d_in[i]; break;  // [4,256,1,128,128]
            case 1024:     u    = (const float*)d_in[i]; break;  // [4,256]
            case 491520:   W    = (const float*)d_in[i]; break;  // [49152,10]
            case 10:       bias = (const float*)d_in[i]; break;  // [10]
            default: break;
        }
    }

    masked_logits_kernel<<<NTILES * NGRP, 256>>>(zl, x, bern, W);
    reduce_kernel<<<(NVALS + 255) / 256, 256>>>();
    finalize_kernel<<<1, NB>>>(y, u, bias, (float*)d_out);
}